// round 8
// baseline (speedup 1.0000x reference)
#include <cuda_runtime.h>
#include <math.h>
#include <stdint.h>

#define T_ 512
#define B_ 64
#define V_ 256
#define H_ 1024
#define G_ 4096   // 4*H
#define TB_ (T_*B_)
#define NCTA 128

// ---------------- scratch (__device__ globals; no allocation allowed) ----------------
__device__ float s_Whh[3*4096*1024];   // tf32-rounded Whh for layers 0..2
__device__ float s_Wih[2*4096*1024];   // tf32-rounded Wih for layers 1..2
__device__ float s_Wout[256*1024];     // tf32-rounded Wout
__device__ float s_gb[3*4096];         // bih+bhh per layer
__device__ int   s_tok[TB_];           // argmax of one-hot inputs
__device__ float s_h[2*B_*H_];         // ping-pong hidden state (tf32-rounded)
__device__ float s_Y[512*64*1024];     // current layer output sequence [t][b][H]
__device__ float s_Gin[512*64*4096];   // precomputed input gates [t][b][4H]
__device__ unsigned g_cnt;             // grid barrier arrive counter (zero-init)
__device__ volatile unsigned g_gen;    // grid barrier generation (zero-init)

// ---------------- helpers ----------------
__device__ __forceinline__ float tf32r(float x) {
    float y;
    asm("cvt.rna.tf32.f32 %0, %1;" : "=f"(y) : "f"(x));
    return y;
}

__device__ __forceinline__ void mma8(float* c, const float* a, const float* b) {
    asm("mma.sync.aligned.m16n8k8.row.col.f32.tf32.tf32.f32 "
        "{%0,%1,%2,%3}, {%4,%5,%6,%7}, {%8,%9}, {%0,%1,%2,%3};"
        : "+f"(c[0]), "+f"(c[1]), "+f"(c[2]), "+f"(c[3])
        : "r"(__float_as_uint(a[0])), "r"(__float_as_uint(a[1])),
          "r"(__float_as_uint(a[2])), "r"(__float_as_uint(a[3])),
          "r"(__float_as_uint(b[0])), "r"(__float_as_uint(b[1])));
}

__device__ __forceinline__ float sigmoidf_(float x) {
    return 1.0f / (1.0f + expf(-x));
}

// software grid barrier (all NCTA CTAs co-resident: NCTA=128 <= 148 SMs, 1 CTA/SM)
__device__ __forceinline__ void grid_sync_() {
    __syncthreads();
    if (threadIdx.x == 0) {
        __threadfence();
        unsigned g = g_gen;                 // read generation BEFORE arriving
        unsigned a = atomicAdd(&g_cnt, 1u);
        if (a == gridDim.x - 1) {
            atomicExch(&g_cnt, 0u);
            __threadfence();
            g_gen = g + 1;
        } else {
            while (g_gen == g) { __nanosleep(32); }
        }
        __threadfence();
    }
    __syncthreads();
}

// ---------------- prep: tokens, round weights to tf32, bias sums ----------------
__global__ void prep_kernel(const float* __restrict__ inputs,
                            const float* __restrict__ Whh0,
                            const float* __restrict__ bih0, const float* __restrict__ bhh0,
                            const float* __restrict__ Wih_rest, const float* __restrict__ Whh_rest,
                            const float* __restrict__ bih_rest, const float* __restrict__ bhh_rest,
                            const float* __restrict__ Wout) {
    const int stride = gridDim.x * blockDim.x;
    const int i0 = blockIdx.x * blockDim.x + threadIdx.x;

    for (int i = i0; i < TB_; i += stride) {
        const float4* r = reinterpret_cast<const float4*>(inputs + (size_t)i * V_);
        int tk = 0;
        #pragma unroll 4
        for (int j = 0; j < V_ / 4; j++) {
            float4 v = r[j];
            if (v.x > 0.5f) tk = 4 * j + 0;
            if (v.y > 0.5f) tk = 4 * j + 1;
            if (v.z > 0.5f) tk = 4 * j + 2;
            if (v.w > 0.5f) tk = 4 * j + 3;
        }
        s_tok[i] = tk;
    }

    const int GH = G_ * H_;
    for (int i = i0; i < GH; i += stride) s_Whh[i] = tf32r(Whh0[i]);
    for (int i = i0; i < 2 * GH; i += stride) {
        s_Whh[GH + i] = tf32r(Whh_rest[i]);
        s_Wih[i] = tf32r(Wih_rest[i]);
    }
    for (int i = i0; i < V_ * H_; i += stride) s_Wout[i] = tf32r(Wout[i]);
    for (int i = i0; i < G_; i += stride) {
        s_gb[i]          = bih0[i] + bhh0[i];
        s_gb[G_ + i]     = bih_rest[i] + bhh_rest[i];
        s_gb[2 * G_ + i] = bih_rest[G_ + i] + bhh_rest[G_ + i];
    }
}

// ---------------- big time-parallel GEMM: C[M,N] = A[M,1024] @ Bw[N,1024]^T + bias ----------------
__global__ __launch_bounds__(256) void gemm_big_kernel(
    const float* __restrict__ A,
    const float* __restrict__ Bw,
    const float* __restrict__ bias,
    float* __restrict__ Cout,
    const int mode) {
    __shared__ float As[128][36];
    __shared__ float Bs[128][36];
    const int tid = threadIdx.x;
    const int wid = tid >> 5, lane = tid & 31;
    const int gr = lane >> 2, tg = lane & 3;
    const int wm = wid & 3;
    const int wn = wid >> 2;
    const int m0 = blockIdx.y * 128;
    const int n0 = blockIdx.x * 128;

    float acc[2][8][4];
    #pragma unroll
    for (int i = 0; i < 2; i++)
        #pragma unroll
        for (int j = 0; j < 8; j++)
            #pragma unroll
            for (int e = 0; e < 4; e++) acc[i][j][e] = 0.0f;

    for (int kc = 0; kc < H_; kc += 32) {
        #pragma unroll
        for (int it = 0; it < 4; it++) {
            int q = tid + 256 * it;
            int r = q >> 3, c4 = (q & 7) * 4;
            *reinterpret_cast<float4*>(&As[r][c4]) =
                *reinterpret_cast<const float4*>(A + (size_t)(m0 + r) * H_ + kc + c4);
            *reinterpret_cast<float4*>(&Bs[r][c4]) =
                *reinterpret_cast<const float4*>(Bw + (size_t)(n0 + r) * H_ + kc + c4);
        }
        __syncthreads();
        #pragma unroll
        for (int ks = 0; ks < 32; ks += 8) {
            float a[2][4];
            #pragma unroll
            for (int mf = 0; mf < 2; mf++) {
                int mr = wm * 32 + mf * 16 + gr;
                a[mf][0] = As[mr][ks + tg];
                a[mf][1] = As[mr + 8][ks + tg];
                a[mf][2] = As[mr][ks + tg + 4];
                a[mf][3] = As[mr + 8][ks + tg + 4];
            }
            #pragma unroll
            for (int nf = 0; nf < 8; nf++) {
                int nr = wn * 64 + nf * 8 + gr;
                float b[2] = { Bs[nr][ks + tg], Bs[nr][ks + tg + 4] };
                #pragma unroll
                for (int mf = 0; mf < 2; mf++) mma8(acc[mf][nf], a[mf], b);
            }
        }
        __syncthreads();
    }

    #pragma unroll
    for (int mf = 0; mf < 2; mf++) {
        #pragma unroll
        for (int nf = 0; nf < 8; nf++) {
            #pragma unroll
            for (int e = 0; e < 4; e++) {
                int m = m0 + wm * 32 + mf * 16 + gr + ((e >= 2) ? 8 : 0);
                int n = n0 + wn * 64 + nf * 8 + 2 * tg + (e & 1);
                float v = acc[mf][nf][e] + bias[n];
                if (mode == 0) {
                    Cout[(size_t)m * G_ + n] = v;
                } else {
                    int t = m >> 6, b = m & 63;
                    Cout[(size_t)b * (V_ * T_) + (size_t)n * T_ + t] = v;
                }
            }
        }
    }
}

// ---------------- persistent per-layer recurrent kernel ----------------
// 128 CTAs; CTA blk owns h-cols [blk*8, blk*8+8) and their 4 gate rows (32 rows).
// Whh slice (32x1024 fp32 = 128KB) cached in smem for the WHOLE layer.
// c state lives in registers. h double-buffered in global (read t&1, write (t+1)&1).
// Dynamic smem layout (floats):
//   Bsm[32][1028]  (Whh slice, pad 4 for conflict-free frag loads)
//   Ash[2][64][68] (h chunk double buffer, k-chunk = 64)
//   gbf[32][65]    (gate staging for pointwise)
#define BSM_F   (32*1028)
#define ASH_F   (2*64*68)
#define GBF_F   (32*65)
#define SMEM_BYTES ((BSM_F + ASH_F + GBF_F) * 4)

__global__ __launch_bounds__(256, 1) void layer_kernel(
    const float* __restrict__ Whh,        // s_Whh + l*G*H
    const float* __restrict__ gin_extra,  // l==0: Wih0 (fp32), else s_Gin
    const float* __restrict__ gb,         // s_gb + l*G (used for l==0 only)
    const int* __restrict__ lengths,
    const int l) {
    extern __shared__ float sm[];
    float* Bsm = sm;                  // [32][1028]
    float* Ash = sm + BSM_F;          // [2][64][68]
    float* gbf = Ash + ASH_F;         // [32][65]

    const int tid = threadIdx.x;
    const int wid = tid >> 5, lane = tid & 31;
    const int gr = lane >> 2, tg = lane & 3;
    const int wm = wid & 3;           // batch 16-group
    const int wn = wid >> 2;          // n 16-group (0..1)
    const int blk = blockIdx.x;

    // ---- phase 0: cache Whh slice in smem; row j -> gate (j>>3), col blk*8+(j&7)
    #pragma unroll 4
    for (int it = 0; it < 32; it++) {
        int q = tid + 256 * it;       // 0..8191 float4s
        int r = q >> 8;               // 0..31
        int c4 = (q & 255) * 4;       // 0..1020
        int grow = (r >> 3) * H_ + blk * 8 + (r & 7);
        *reinterpret_cast<float4*>(&Bsm[r * 1028 + c4]) =
            *reinterpret_cast<const float4*>(&Whh[(size_t)grow * H_ + c4]);
    }

    // ---- per-layer zero init: c in regs, owned h slice in buffer 0
    float creg[2] = {0.0f, 0.0f};
    #pragma unroll
    for (int e = 0; e < 2; e++) {
        int eid = tid + 256 * e;
        int b = eid >> 3, hc = eid & 7;
        s_h[b * H_ + blk * 8 + hc] = 0.0f;
    }
    grid_sync_();   // all zeros visible before t=0 reads

    for (int t = 0; t < T_; t++) {
        const float* hrd = s_h + (size_t)(t & 1) * (B_ * H_);
        float*       hwr = s_h + (size_t)((t + 1) & 1) * (B_ * H_);

        float acc[2][4];
        #pragma unroll
        for (int j = 0; j < 2; j++)
            #pragma unroll
            for (int e = 0; e < 4; e++) acc[j][e] = 0.0f;

        // preload chunk 0 of h
        #pragma unroll
        for (int it = 0; it < 4; it++) {
            int q = tid + 256 * it;
            int r = q >> 4, c4 = (q & 15) * 4;
            *reinterpret_cast<float4*>(&Ash[r * 68 + c4]) =
                *reinterpret_cast<const float4*>(&hrd[r * H_ + c4]);
        }
        __syncthreads();

        int buf = 0;
        for (int kc = 0; kc < H_; kc += 64) {
            if (kc + 64 < H_) {
                #pragma unroll
                for (int it = 0; it < 4; it++) {
                    int q = tid + 256 * it;
                    int r = q >> 4, c4 = (q & 15) * 4;
                    *reinterpret_cast<float4*>(&Ash[(buf ^ 1) * (64 * 68) + r * 68 + c4]) =
                        *reinterpret_cast<const float4*>(&hrd[r * H_ + kc + 64 + c4]);
                }
            }
            const float* Ab = Ash + buf * (64 * 68);
            #pragma unroll
            for (int ks = 0; ks < 64; ks += 8) {
                float a[4];
                int mr = wm * 16 + gr;
                a[0] = Ab[mr * 68 + ks + tg];
                a[1] = Ab[(mr + 8) * 68 + ks + tg];
                a[2] = Ab[mr * 68 + ks + tg + 4];
                a[3] = Ab[(mr + 8) * 68 + ks + tg + 4];
                #pragma unroll
                for (int nf = 0; nf < 2; nf++) {
                    int nr = wn * 16 + nf * 8 + gr;
                    float b2[2] = { Bsm[nr * 1028 + kc + ks + tg],
                                    Bsm[nr * 1028 + kc + ks + tg + 4] };
                    mma8(acc[nf], a, b2);
                }
            }
            __syncthreads();
            buf ^= 1;
        }

        // stage gates -> gbf[n][batch]
        #pragma unroll
        for (int nf = 0; nf < 2; nf++) {
            #pragma unroll
            for (int e = 0; e < 4; e++) {
                int m = wm * 16 + gr + ((e >= 2) ? 8 : 0);
                int n = wn * 16 + nf * 8 + 2 * tg + (e & 1);
                gbf[n * 65 + m] = acc[nf][e];
            }
        }
        __syncthreads();

        // fused LSTM pointwise: 64 batches x 8 owned h-cols, 2 per thread
        #pragma unroll
        for (int e = 0; e < 2; e++) {
            int eid = tid + 256 * e;
            int b = eid >> 3, hc = eid & 7;
            int col = blk * 8 + hc;
            float xi = gbf[hc * 65 + b];
            float xf = gbf[(8 + hc) * 65 + b];
            float xg = gbf[(16 + hc) * 65 + b];
            float xo = gbf[(24 + hc) * 65 + b];
            if (l == 0) {
                int tk = s_tok[t * B_ + b];
                xi += gin_extra[(size_t)col * V_ + tk]            + gb[col];
                xf += gin_extra[(size_t)(H_ + col) * V_ + tk]     + gb[H_ + col];
                xg += gin_extra[(size_t)(2 * H_ + col) * V_ + tk] + gb[2 * H_ + col];
                xo += gin_extra[(size_t)(3 * H_ + col) * V_ + tk] + gb[3 * H_ + col];
            } else {
                const float* gp = gin_extra + (size_t)(t * B_ + b) * G_;
                xi += gp[col];
                xf += gp[H_ + col];
                xg += gp[2 * H_ + col];
                xo += gp[3 * H_ + col];
            }
            float ig = sigmoidf_(xi);
            float fg = sigmoidf_(xf);
            float og = sigmoidf_(xo);
            float gg = tanhf(xg);
            float c2 = fg * creg[e] + ig * gg;
            creg[e] = c2;
            float h2r = tf32r(og * tanhf(c2));  // consumers are tf32 mma -> pre-round
            hwr[b * H_ + col] = h2r;
            float yv = h2r;
            if (l == 2 && t >= lengths[b]) yv = 0.0f;  // mask OUTPUT only
            s_Y[(size_t)(t * B_ + b) * H_ + col] = yv;
        }
        grid_sync_();   // h(t+1) visible to all CTAs before step t+1
    }
}

// ---------------- launch ----------------
extern "C" void kernel_launch(void* const* d_in, const int* in_sizes, int n_in,
                              void* d_out, int out_size) {
    const float* inputs    = (const float*)d_in[0];
    const int*   lengths   = (const int*)  d_in[1];
    const float* Wih0      = (const float*)d_in[2];
    const float* Whh0      = (const float*)d_in[3];
    const float* bih0      = (const float*)d_in[4];
    const float* bhh0      = (const float*)d_in[5];
    const float* Wih_rest  = (const float*)d_in[6];
    const float* Whh_rest  = (const float*)d_in[7];
    const float* bih_rest  = (const float*)d_in[8];
    const float* bhh_rest  = (const float*)d_in[9];
    const float* Wout      = (const float*)d_in[10];
    const float* bout      = (const float*)d_in[11];
    float* out = (float*)d_out;

    void *pWhh_, *pWih_, *pWout_, *pgb_, *pY_, *pGin_;
    cudaGetSymbolAddress(&pWhh_,  s_Whh);
    cudaGetSymbolAddress(&pWih_,  s_Wih);
    cudaGetSymbolAddress(&pWout_, s_Wout);
    cudaGetSymbolAddress(&pgb_,   s_gb);
    cudaGetSymbolAddress(&pY_,    s_Y);
    cudaGetSymbolAddress(&pGin_,  s_Gin);
    const float* pWhh  = (const float*)pWhh_;
    const float* pWih  = (const float*)pWih_;
    const float* pWout = (const float*)pWout_;
    const float* pgb   = (const float*)pgb_;
    const float* pY    = (const float*)pY_;
    float*       pGin  = (float*)pGin_;

    cudaFuncSetAttribute(layer_kernel,
                         cudaFuncAttributeMaxDynamicSharedMemorySize, SMEM_BYTES);

    prep_kernel<<<1024, 256>>>(inputs, Whh0, bih0, bhh0,
                               Wih_rest, Whh_rest, bih_rest, bhh_rest, Wout);

    for (int l = 0; l < 3; l++) {
        if (l >= 1) {
            dim3 g(32, 256);
            gemm_big_kernel<<<g, 256>>>(pY, pWih + (size_t)(l - 1) * G_ * H_,
                                        pgb + (size_t)l * G_, pGin, 0);
        }
        const float* gin_extra = (l == 0) ? Wih0 : (const float*)pGin;
        layer_kernel<<<NCTA, 256, SMEM_BYTES>>>(pWhh + (size_t)l * G_ * H_, gin_extra,
                                                pgb + (size_t)l * G_, lengths, l);
    }

    dim3 gp(2, 256);
    gemm_big_kernel<<<gp, 256>>>(pY, pWout, bout, out, 1);
}

// round 11
// speedup vs baseline: 1.4082x; 1.4082x over previous
#include <cuda_runtime.h>
#include <math.h>
#include <stdint.h>

#define T_ 512
#define B_ 64
#define V_ 256
#define H_ 1024
#define G_ 4096   // 4*H
#define TB_ (T_*B_)
#define NCTA 128

#define CHUNK 64
#define NCH   (H_/CHUNK)      // 16
#define BSM_STRIDE 1028       // 1028 % 32 == 4 -> conflict-free frag reads
#define ASH_STRIDE 68         // 68 % 32 == 4
#define GS_STRIDE  40         // 40 % 32 == 8 -> conflict-free pointwise reads
#define BSM_F   (32*BSM_STRIDE)        // 32896 floats
#define REGION_F (8*64*GS_STRIDE)      // 20480 floats (>= 4 Ash bufs of 64*68)
#define SMEM_BYTES ((BSM_F + REGION_F)*4)   // 213504 B

// ---------------- scratch (__device__ globals; no allocation allowed) ----------------
__device__ float s_Whh[3*4096*1024];   // tf32-rounded Whh for layers 0..2
__device__ float s_Wih[2*4096*1024];   // tf32-rounded Wih for layers 1..2
__device__ float s_Wout[256*1024];     // tf32-rounded Wout
__device__ float s_gb[3*4096];         // bih+bhh per layer
__device__ int   s_tok[TB_];           // argmax of one-hot inputs
__device__ float s_h[2*B_*H_];         // ping-pong hidden state (tf32-rounded)
__device__ float s_Y[512*64*1024];     // current layer output sequence [t][b][H]
__device__ float s_Gin[512*64*4096];   // precomputed input gates [t][b][4H]
__device__ unsigned g_cnt;             // grid barrier arrive counter (zero-init)
__device__ volatile unsigned g_gen;    // grid barrier generation (zero-init)

// ---------------- helpers ----------------
__device__ __forceinline__ float tf32r(float x) {
    float y;
    asm("cvt.rna.tf32.f32 %0, %1;" : "=f"(y) : "f"(x));
    return y;
}

__device__ __forceinline__ void mma8(float* c, const float* a, const float* b) {
    asm("mma.sync.aligned.m16n8k8.row.col.f32.tf32.tf32.f32 "
        "{%0,%1,%2,%3}, {%4,%5,%6,%7}, {%8,%9}, {%0,%1,%2,%3};"
        : "+f"(c[0]), "+f"(c[1]), "+f"(c[2]), "+f"(c[3])
        : "r"(__float_as_uint(a[0])), "r"(__float_as_uint(a[1])),
          "r"(__float_as_uint(a[2])), "r"(__float_as_uint(a[3])),
          "r"(__float_as_uint(b[0])), "r"(__float_as_uint(b[1])));
}

__device__ __forceinline__ float sigmoidf_(float x) {
    return 1.0f / (1.0f + expf(-x));
}

__device__ __forceinline__ uint32_t smem_u32(const void* p) {
    uint32_t a;
    asm("{ .reg .u64 t; cvta.to.shared.u64 t, %1; cvt.u32.u64 %0, t; }"
        : "=r"(a) : "l"(p));
    return a;
}

__device__ __forceinline__ void cp16(uint32_t dst, const void* src) {
    asm volatile("cp.async.cg.shared.global [%0], [%1], 16;"
                 :: "r"(dst), "l"(src) : "memory");
}
__device__ __forceinline__ void cp_commit() {
    asm volatile("cp.async.commit_group;" ::: "memory");
}
__device__ __forceinline__ void cp_wait2() {
    asm volatile("cp.async.wait_group 2;" ::: "memory");
}

// software grid barrier (NCTA=128 CTAs, 1 per SM, all co-resident)
__device__ __forceinline__ void grid_sync_() {
    __syncthreads();
    if (threadIdx.x == 0) {
        __threadfence();
        unsigned g = g_gen;                 // read generation BEFORE arriving
        unsigned a = atomicAdd(&g_cnt, 1u);
        if (a == gridDim.x - 1) {
            atomicExch(&g_cnt, 0u);
            __threadfence();
            g_gen = g + 1;
        } else {
            while (g_gen == g) { __nanosleep(32); }
        }
        __threadfence();
    }
    __syncthreads();
}

// ---------------- prep: tokens, round weights to tf32, bias sums ----------------
__global__ void prep_kernel(const float* __restrict__ inputs,
                            const float* __restrict__ Whh0,
                            const float* __restrict__ bih0, const float* __restrict__ bhh0,
                            const float* __restrict__ Wih_rest, const float* __restrict__ Whh_rest,
                            const float* __restrict__ bih_rest, const float* __restrict__ bhh_rest,
                            const float* __restrict__ Wout) {
    const int stride = gridDim.x * blockDim.x;
    const int i0 = blockIdx.x * blockDim.x + threadIdx.x;

    for (int i = i0; i < TB_; i += stride) {
        const float4* r = reinterpret_cast<const float4*>(inputs + (size_t)i * V_);
        int tk = 0;
        #pragma unroll 4
        for (int j = 0; j < V_ / 4; j++) {
            float4 v = r[j];
            if (v.x > 0.5f) tk = 4 * j + 0;
            if (v.y > 0.5f) tk = 4 * j + 1;
            if (v.z > 0.5f) tk = 4 * j + 2;
            if (v.w > 0.5f) tk = 4 * j + 3;
        }
        s_tok[i] = tk;
    }

    const int GH = G_ * H_;
    for (int i = i0; i < GH; i += stride) s_Whh[i] = tf32r(Whh0[i]);
    for (int i = i0; i < 2 * GH; i += stride) {
        s_Whh[GH + i] = tf32r(Whh_rest[i]);
        s_Wih[i] = tf32r(Wih_rest[i]);
    }
    for (int i = i0; i < V_ * H_; i += stride) s_Wout[i] = tf32r(Wout[i]);
    for (int i = i0; i < G_; i += stride) {
        s_gb[i]          = bih0[i] + bhh0[i];
        s_gb[G_ + i]     = bih_rest[i] + bhh_rest[i];
        s_gb[2 * G_ + i] = bih_rest[G_ + i] + bhh_rest[G_ + i];
    }
}

// ---------------- big time-parallel GEMM: C[M,N] = A[M,1024] @ Bw[N,1024]^T + bias ----------------
__global__ __launch_bounds__(256) void gemm_big_kernel(
    const float* __restrict__ A,
    const float* __restrict__ Bw,
    const float* __restrict__ bias,
    float* __restrict__ Cout,
    const int mode) {
    __shared__ float As[128][36];
    __shared__ float Bs[128][36];
    const int tid = threadIdx.x;
    const int wid = tid >> 5, lane = tid & 31;
    const int gr = lane >> 2, tg = lane & 3;
    const int wm = wid & 3;
    const int wn = wid >> 2;
    const int m0 = blockIdx.y * 128;
    const int n0 = blockIdx.x * 128;

    float acc[2][8][4];
    #pragma unroll
    for (int i = 0; i < 2; i++)
        #pragma unroll
        for (int j = 0; j < 8; j++)
            #pragma unroll
            for (int e = 0; e < 4; e++) acc[i][j][e] = 0.0f;

    for (int kc = 0; kc < H_; kc += 32) {
        #pragma unroll
        for (int it = 0; it < 4; it++) {
            int q = tid + 256 * it;
            int r = q >> 3, c4 = (q & 7) * 4;
            *reinterpret_cast<float4*>(&As[r][c4]) =
                *reinterpret_cast<const float4*>(A + (size_t)(m0 + r) * H_ + kc + c4);
            *reinterpret_cast<float4*>(&Bs[r][c4]) =
                *reinterpret_cast<const float4*>(Bw + (size_t)(n0 + r) * H_ + kc + c4);
        }
        __syncthreads();
        #pragma unroll
        for (int ks = 0; ks < 32; ks += 8) {
            float a[2][4];
            #pragma unroll
            for (int mf = 0; mf < 2; mf++) {
                int mr = wm * 32 + mf * 16 + gr;
                a[mf][0] = As[mr][ks + tg];
                a[mf][1] = As[mr + 8][ks + tg];
                a[mf][2] = As[mr][ks + tg + 4];
                a[mf][3] = As[mr + 8][ks + tg + 4];
            }
            #pragma unroll
            for (int nf = 0; nf < 8; nf++) {
                int nr = wn * 64 + nf * 8 + gr;
                float b[2] = { Bs[nr][ks + tg], Bs[nr][ks + tg + 4] };
                #pragma unroll
                for (int mf = 0; mf < 2; mf++) mma8(acc[mf][nf], a[mf], b);
            }
        }
        __syncthreads();
    }

    #pragma unroll
    for (int mf = 0; mf < 2; mf++) {
        #pragma unroll
        for (int nf = 0; nf < 8; nf++) {
            #pragma unroll
            for (int e = 0; e < 4; e++) {
                int m = m0 + wm * 32 + mf * 16 + gr + ((e >= 2) ? 8 : 0);
                int n = n0 + wn * 64 + nf * 8 + 2 * tg + (e & 1);
                float v = acc[mf][nf][e] + bias[n];
                if (mode == 0) {
                    Cout[(size_t)m * G_ + n] = v;
                } else {
                    int t = m >> 6, b = m & 63;
                    Cout[(size_t)b * (V_ * T_) + (size_t)n * T_ + t] = v;
                }
            }
        }
    }
}

// ---------------- persistent per-layer recurrent kernel (K-split warps) ----------------
// 128 CTAs; CTA blk owns h-cols [blk*8, blk*8+8) and their 4 gate rows (32 rows).
// All 8 warps compute the FULL 64x32 output over disjoint k-slices (8 cols/chunk each);
// partials reduced through smem. Whh slice (32x1024) smem-resident for the whole layer.
// h streamed with cp.async, 4 buffers, 3-chunk lookahead. c-state in registers.
__global__ __launch_bounds__(256, 1) void layer_kernel(
    const float* __restrict__ Whh,        // s_Whh + l*G*H
    const float* __restrict__ gin_extra,  // l==0: Wih0 (fp32), else s_Gin
    const float* __restrict__ gb,         // s_gb + l*G (used for l==0 only)
    const int* __restrict__ lengths,
    const int l) {
    extern __shared__ float sm[];
    float* Bsm  = sm;                 // [32][1028]
    float* Ash  = sm + BSM_F;         // 4 bufs of [64][68]; aliased by gsum
    float* gsum = Ash;                // [8][64][40]

    const int tid = threadIdx.x;
    const int wid = tid >> 5, lane = tid & 31;
    const int gr = lane >> 2, tg = lane & 3;
    const int blk = blockIdx.x;
    const uint32_t ash_u = smem_u32(Ash);

    // ---- cache Whh slice: Bsm row r <-> gate (r>>3), h-col blk*8+(r&7)
    #pragma unroll 4
    for (int it = 0; it < 32; it++) {
        int q = tid + 256 * it;       // 8192 float4s
        int r = q >> 8;
        int c4 = (q & 255) * 4;
        int grow = (r >> 3) * H_ + blk * 8 + (r & 7);
        *reinterpret_cast<float4*>(&Bsm[r * BSM_STRIDE + c4]) =
            *reinterpret_cast<const float4*>(&Whh[(size_t)grow * H_ + c4]);
    }

    // ---- hoist pointwise-lane invariants
    int pb[2], phc[2], plen[2];
    float gbr[2][4];
    #pragma unroll
    for (int e = 0; e < 2; e++) {
        int eid = tid + 256 * e;
        pb[e] = eid >> 3; phc[e] = eid & 7;
        int col = blk * 8 + phc[e];
        gbr[e][0] = gb[col];
        gbr[e][1] = gb[H_ + col];
        gbr[e][2] = gb[2 * H_ + col];
        gbr[e][3] = gb[3 * H_ + col];
        plen[e] = lengths[pb[e]];
        s_h[pb[e] * H_ + col] = 0.0f;   // zero buffer 0 (read at t=0)
    }
    float creg[2] = {0.0f, 0.0f};
    grid_sync_();   // zeros visible before t=0

    for (int t = 0; t < T_; t++) {
        const float* hrd = s_h + (size_t)(t & 1) * (B_ * H_);
        float*       hwr = s_h + (size_t)((t + 1) & 1) * (B_ * H_);

        // ---- prefetch Gin into regs (independent of h)
        float gx[2][4];
        if (l == 0) {
            #pragma unroll
            for (int e = 0; e < 2; e++) {
                int tk = s_tok[t * B_ + pb[e]];
                int col = blk * 8 + phc[e];
                gx[e][0] = gin_extra[(size_t)col * V_ + tk]            + gbr[e][0];
                gx[e][1] = gin_extra[(size_t)(H_ + col) * V_ + tk]     + gbr[e][1];
                gx[e][2] = gin_extra[(size_t)(2 * H_ + col) * V_ + tk] + gbr[e][2];
                gx[e][3] = gin_extra[(size_t)(3 * H_ + col) * V_ + tk] + gbr[e][3];
            }
        } else {
            #pragma unroll
            for (int e = 0; e < 2; e++) {
                const float* gp = gin_extra + (size_t)(t * B_ + pb[e]) * G_ + blk * 8 + phc[e];
                gx[e][0] = gp[0];
                gx[e][1] = gp[H_];
                gx[e][2] = gp[2 * H_];
                gx[e][3] = gp[3 * H_];
            }
        }

        float acc[4][4][4];
        #pragma unroll
        for (int mf = 0; mf < 4; mf++)
            #pragma unroll
            for (int nf = 0; nf < 4; nf++)
                #pragma unroll
                for (int e = 0; e < 4; e++) acc[mf][nf][e] = 0.0f;

        // ---- prologue: prefetch chunks 0..2 (4 cp16 per thread per chunk)
        #pragma unroll
        for (int p = 0; p < 3; p++) {
            #pragma unroll
            for (int i = 0; i < 4; i++) {
                int q = tid + 256 * i;
                int r = q >> 4, cp = (q & 15) * 4;
                cp16(ash_u + ((p & 3) * (64 * ASH_STRIDE) + r * ASH_STRIDE + cp) * 4,
                     hrd + r * H_ + p * CHUNK + cp);
            }
            cp_commit();
        }

        // ---- mainloop over 16 chunks; each warp consumes its 8-col k-slice
        for (int c = 0; c < NCH; c++) {
            cp_wait2();
            __syncthreads();
            const float* Ab = Ash + (c & 3) * (64 * ASH_STRIDE);
            const int kl = wid * 8;           // warp's cols inside chunk
            const int kb = c * CHUNK + kl;    // global k base

            float a[4][4], bf[4][2];
            #pragma unroll
            for (int mf = 0; mf < 4; mf++) {
                int mr = mf * 16 + gr;
                a[mf][0] = Ab[mr * ASH_STRIDE + kl + tg];
                a[mf][1] = Ab[(mr + 8) * ASH_STRIDE + kl + tg];
                a[mf][2] = Ab[mr * ASH_STRIDE + kl + tg + 4];
                a[mf][3] = Ab[(mr + 8) * ASH_STRIDE + kl + tg + 4];
            }
            #pragma unroll
            for (int nf = 0; nf < 4; nf++) {
                int nr = nf * 8 + gr;
                bf[nf][0] = Bsm[nr * BSM_STRIDE + kb + tg];
                bf[nf][1] = Bsm[nr * BSM_STRIDE + kb + tg + 4];
            }
            #pragma unroll
            for (int mf = 0; mf < 4; mf++)
                #pragma unroll
                for (int nf = 0; nf < 4; nf++)
                    mma8(acc[mf][nf], a[mf], bf[nf]);

            // prefetch chunk c+3 (empty commit at tail keeps group math uniform)
            if (c + 3 < NCH) {
                int p = c + 3;
                #pragma unroll
                for (int i = 0; i < 4; i++) {
                    int q = tid + 256 * i;
                    int r = q >> 4, cp = (q & 15) * 4;
                    cp16(ash_u + ((p & 3) * (64 * ASH_STRIDE) + r * ASH_STRIDE + cp) * 4,
                         hrd + r * H_ + p * CHUNK + cp);
                }
            }
            cp_commit();
        }
        __syncthreads();   // all frag reads done; gsum aliases Ash

        // ---- store partials: gsum[w][m(batch)][n(gate-row)]
        #pragma unroll
        for (int mf = 0; mf < 4; mf++)
            #pragma unroll
            for (int nf = 0; nf < 4; nf++) {
                int m0 = mf * 16 + gr, n0 = nf * 8 + 2 * tg;
                *reinterpret_cast<float2*>(&gsum[(wid * 64 + m0) * GS_STRIDE + n0]) =
                    make_float2(acc[mf][nf][0], acc[mf][nf][1]);
                *reinterpret_cast<float2*>(&gsum[(wid * 64 + m0 + 8) * GS_STRIDE + n0]) =
                    make_float2(acc[mf][nf][2], acc[mf][nf][3]);
            }
        __syncthreads();

        // ---- reduce 8 partials + fused LSTM pointwise
        #pragma unroll
        for (int e = 0; e < 2; e++) {
            int b = pb[e], hc = phc[e];
            int col = blk * 8 + hc;
            float xi = gx[e][0], xf = gx[e][1], xg = gx[e][2], xo = gx[e][3];
            #pragma unroll
            for (int w = 0; w < 8; w++) {
                const float* gs = gsum + (w * 64 + b) * GS_STRIDE;
                xi += gs[hc];
                xf += gs[8 + hc];
                xg += gs[16 + hc];
                xo += gs[24 + hc];
            }
            float ig = sigmoidf_(xi);
            float fg = sigmoidf_(xf);
            float og = sigmoidf_(xo);
            float gg = tanhf(xg);
            float c2 = fg * creg[e] + ig * gg;
            creg[e] = c2;
            float h2r = tf32r(og * tanhf(c2));  // consumers are tf32 mma -> pre-round
            hwr[b * H_ + col] = h2r;
            float yv = h2r;
            if (l == 2 && t >= plen[e]) yv = 0.0f;  // mask OUTPUT only
            s_Y[(size_t)(t * B_ + b) * H_ + col] = yv;
        }
        grid_sync_();   // h(t+1) visible to all CTAs before step t+1
    }
}

// ---------------- launch ----------------
extern "C" void kernel_launch(void* const* d_in, const int* in_sizes, int n_in,
                              void* d_out, int out_size) {
    const float* inputs    = (const float*)d_in[0];
    const int*   lengths   = (const int*)  d_in[1];
    const float* Wih0      = (const float*)d_in[2];
    const float* Whh0      = (const float*)d_in[3];
    const float* bih0      = (const float*)d_in[4];
    const float* bhh0      = (const float*)d_in[5];
    const float* Wih_rest  = (const float*)d_in[6];
    const float* Whh_rest  = (const float*)d_in[7];
    const float* bih_rest  = (const float*)d_in[8];
    const float* bhh_rest  = (const float*)d_in[9];
    const float* Wout      = (const float*)d_in[10];
    const float* bout      = (const float*)d_in[11];
    float* out = (float*)d_out;

    void *pWhh_, *pWih_, *pWout_, *pgb_, *pY_, *pGin_;
    cudaGetSymbolAddress(&pWhh_,  s_Whh);
    cudaGetSymbolAddress(&pWih_,  s_Wih);
    cudaGetSymbolAddress(&pWout_, s_Wout);
    cudaGetSymbolAddress(&pgb_,   s_gb);
    cudaGetSymbolAddress(&pY_,    s_Y);
    cudaGetSymbolAddress(&pGin_,  s_Gin);
    const float* pWhh  = (const float*)pWhh_;
    const float* pWih  = (const float*)pWih_;
    const float* pWout = (const float*)pWout_;
    const float* pgb   = (const float*)pgb_;
    const float* pY    = (const float*)pY_;
    float*       pGin  = (float*)pGin_;

    cudaFuncSetAttribute(layer_kernel,
                         cudaFuncAttributeMaxDynamicSharedMemorySize, SMEM_BYTES);

    prep_kernel<<<1024, 256>>>(inputs, Whh0, bih0, bhh0,
                               Wih_rest, Whh_rest, bih_rest, bhh_rest, Wout);

    for (int l = 0; l < 3; l++) {
        if (l >= 1) {
            dim3 g(32, 256);
            gemm_big_kernel<<<g, 256>>>(pY, pWih + (size_t)(l - 1) * G_ * H_,
                                        pgb + (size_t)l * G_, pGin, 0);
        }
        const float* gin_extra = (l == 0) ? Wih0 : (const float*)pGin;
        layer_kernel<<<NCTA, 256, SMEM_BYTES>>>(pWhh + (size_t)l * G_ * H_, gin_extra,
                                                pgb + (size_t)l * G_, lengths, l);
    }

    dim3 gp(2, 256);
    gemm_big_kernel<<<gp, 256>>>(pY, pWout, bout, out, 1);
}